// round 1
// baseline (speedup 1.0000x reference)
#include <cuda_runtime.h>
#include <cstdint>

#define HD 64
#define NMAX 300000

// Scratch (no cudaMalloc allowed) — device globals.
__device__ float g_x[(size_t)NMAX * HD];    // encoded / layer-out features
__device__ float g_y[(size_t)NMAX * HD];    // layer-1 output
__device__ float g_agg[(size_t)NMAX * HD];  // segment-sum accumulator
__device__ float g_cnt[NMAX];               // in-degree (float)

// ---------------------------------------------------------------------------
// reduction helpers (no return value -> REDG, not ATOMG)
// ---------------------------------------------------------------------------
__device__ __forceinline__ void red_add_f32(float* p, float v) {
    asm volatile("red.global.add.f32 [%0], %1;" :: "l"(p), "f"(v) : "memory");
}
__device__ __forceinline__ void red_add_v4(float* p, float4 v) {
    asm volatile("red.global.add.v4.f32 [%0], {%1,%2,%3,%4};"
                 :: "l"(p), "f"(v.x), "f"(v.y), "f"(v.z), "f"(v.w) : "memory");
}

// ---------------------------------------------------------------------------
// zero fill (float4 granularity; all our buffers are /4)
// ---------------------------------------------------------------------------
__global__ void zero_kernel(float* __restrict__ p, long long n4) {
    long long i = (long long)blockIdx.x * blockDim.x + threadIdx.x;
    if (i < n4) reinterpret_cast<float4*>(p)[i] = make_float4(0.f, 0.f, 0.f, 0.f);
}

// ---------------------------------------------------------------------------
// in-degree count
// ---------------------------------------------------------------------------
__global__ void degree_kernel(const int* __restrict__ dst, float* __restrict__ cnt, int E) {
    int i = blockIdx.x * blockDim.x + threadIdx.x;
    if (i < E) red_add_f32(cnt + __ldg(dst + i), 1.0f);
}

// ---------------------------------------------------------------------------
// edge scatter: agg[dst] += x[src]   (16 lanes per edge, float4 each)
// ---------------------------------------------------------------------------
__global__ void scatter_kernel(const float* __restrict__ x, const int* __restrict__ src,
                               const int* __restrict__ dst, float* __restrict__ agg, int E) {
    long long i = (long long)blockIdx.x * blockDim.x + threadIdx.x;
    long long total = (long long)E * 16;
    if (i >= total) return;
    int e = (int)(i >> 4);
    int c = (int)(i & 15);
    int s = __ldg(src + e);
    int d = __ldg(dst + e);
    float4 v = *reinterpret_cast<const float4*>(x + (size_t)s * HD + c * 4);
    red_add_v4(agg + (size_t)d * HD + c * 4, v);
}

// ---------------------------------------------------------------------------
// per-type encoder: out[row] = x[row] @ W[FIN,64] + b    (row per thread)
// ---------------------------------------------------------------------------
template <int FIN>
__global__ __launch_bounds__(128) void encode_kernel(
    const float* __restrict__ x, const float* __restrict__ W,
    const float* __restrict__ b, float* __restrict__ out, int n) {
    __shared__ float sW[FIN * HD];
    __shared__ float sb[HD];
    for (int i = threadIdx.x; i < FIN * HD; i += 128) sW[i] = W[i];
    if (threadIdx.x < HD) sb[threadIdx.x] = b[threadIdx.x];
    __syncthreads();
    int row = blockIdx.x * 128 + threadIdx.x;
    if (row >= n) return;

    float4 acc[16];
#pragma unroll
    for (int c = 0; c < 16; c++) acc[c] = reinterpret_cast<const float4*>(sb)[c];

    const float4* xr = reinterpret_cast<const float4*>(x + (size_t)row * FIN);
#pragma unroll 1
    for (int kc = 0; kc < FIN / 4; kc++) {
        float4 xv = xr[kc];
        float xk[4] = {xv.x, xv.y, xv.z, xv.w};
#pragma unroll
        for (int kk = 0; kk < 4; kk++) {
            const float4* w = reinterpret_cast<const float4*>(sW + (kc * 4 + kk) * HD);
#pragma unroll
            for (int c = 0; c < 16; c++) {
                float4 wv = w[c];
                acc[c].x += xk[kk] * wv.x;
                acc[c].y += xk[kk] * wv.y;
                acc[c].z += xk[kk] * wv.z;
                acc[c].w += xk[kk] * wv.w;
            }
        }
    }
    float4* o = reinterpret_cast<float4*>(out + (size_t)row * HD);
#pragma unroll
    for (int c = 0; c < 16; c++) o[c] = acc[c];
}

// ---------------------------------------------------------------------------
// SAGE combine: out = relu( (agg/max(cnt,1)) @ Wl + x @ Wr + b )
// one full 64-wide output row per thread; both 64x64 weights in SMEM
// ---------------------------------------------------------------------------
__global__ __launch_bounds__(128) void sage_combine_kernel(
    const float* __restrict__ x, const float* __restrict__ agg,
    const float* __restrict__ cnt,
    const float* __restrict__ Wl, const float* __restrict__ Wr,
    const float* __restrict__ b, float* __restrict__ out, int n) {
    __shared__ float sWl[HD * HD];
    __shared__ float sWr[HD * HD];
    __shared__ float sb[HD];
    for (int i = threadIdx.x; i < HD * HD; i += 128) {
        sWl[i] = Wl[i];
        sWr[i] = Wr[i];
    }
    if (threadIdx.x < HD) sb[threadIdx.x] = b[threadIdx.x];
    __syncthreads();
    int row = blockIdx.x * 128 + threadIdx.x;
    if (row >= n) return;

    float inv = 1.0f / fmaxf(__ldg(cnt + row), 1.0f);
    float4 acc[16];
#pragma unroll
    for (int c = 0; c < 16; c++) acc[c] = reinterpret_cast<const float4*>(sb)[c];

    const float4* xr = reinterpret_cast<const float4*>(x + (size_t)row * HD);
    const float4* ar = reinterpret_cast<const float4*>(agg + (size_t)row * HD);
#pragma unroll 1
    for (int kc = 0; kc < 16; kc++) {
        float4 xv = xr[kc];
        float4 av = ar[kc];
        float xk[4] = {xv.x, xv.y, xv.z, xv.w};
        float mk[4] = {av.x * inv, av.y * inv, av.z * inv, av.w * inv};
#pragma unroll
        for (int kk = 0; kk < 4; kk++) {
            int k = kc * 4 + kk;
            const float4* wl = reinterpret_cast<const float4*>(sWl + k * HD);
            const float4* wr = reinterpret_cast<const float4*>(sWr + k * HD);
#pragma unroll
            for (int c = 0; c < 16; c++) {
                float4 l = wl[c];
                float4 r = wr[c];
                acc[c].x += mk[kk] * l.x + xk[kk] * r.x;
                acc[c].y += mk[kk] * l.y + xk[kk] * r.y;
                acc[c].z += mk[kk] * l.z + xk[kk] * r.z;
                acc[c].w += mk[kk] * l.w + xk[kk] * r.w;
            }
        }
    }
    float4* o = reinterpret_cast<float4*>(out + (size_t)row * HD);
#pragma unroll
    for (int c = 0; c < 16; c++) {
        float4 v = acc[c];
        v.x = fmaxf(v.x, 0.f);
        v.y = fmaxf(v.y, 0.f);
        v.z = fmaxf(v.z, 0.f);
        v.w = fmaxf(v.w, 0.f);
        o[c] = v;
    }
}

// ---------------------------------------------------------------------------
// classifier: out = relu(x @ Wc1[64,32] + bc1) @ Wc2[32,2] + bc2
// ---------------------------------------------------------------------------
__global__ __launch_bounds__(128) void classify_kernel(
    const float* __restrict__ x,
    const float* __restrict__ Wc1, const float* __restrict__ bc1,
    const float* __restrict__ Wc2, const float* __restrict__ bc2,
    float* __restrict__ out, int n) {
    __shared__ float sW1[HD * 32];
    __shared__ float sW2[32 * 2];
    __shared__ float sb1[32];
    __shared__ float sb2[2];
    for (int i = threadIdx.x; i < HD * 32; i += 128) sW1[i] = Wc1[i];
    if (threadIdx.x < 64) sW2[threadIdx.x] = Wc2[threadIdx.x];
    if (threadIdx.x < 32) sb1[threadIdx.x] = bc1[threadIdx.x];
    if (threadIdx.x < 2) sb2[threadIdx.x] = bc2[threadIdx.x];
    __syncthreads();
    int row = blockIdx.x * 128 + threadIdx.x;
    if (row >= n) return;

    float4 h[8];
#pragma unroll
    for (int c = 0; c < 8; c++) h[c] = reinterpret_cast<const float4*>(sb1)[c];

    const float4* xr = reinterpret_cast<const float4*>(x + (size_t)row * HD);
#pragma unroll 1
    for (int kc = 0; kc < 16; kc++) {
        float4 xv = xr[kc];
        float xk[4] = {xv.x, xv.y, xv.z, xv.w};
#pragma unroll
        for (int kk = 0; kk < 4; kk++) {
            const float4* w = reinterpret_cast<const float4*>(sW1 + (kc * 4 + kk) * 32);
#pragma unroll
            for (int c = 0; c < 8; c++) {
                float4 wv = w[c];
                h[c].x += xk[kk] * wv.x;
                h[c].y += xk[kk] * wv.y;
                h[c].z += xk[kk] * wv.z;
                h[c].w += xk[kk] * wv.w;
            }
        }
    }
    float o0 = sb2[0], o1 = sb2[1];
    float* hh = reinterpret_cast<float*>(h);
#pragma unroll
    for (int k = 0; k < 32; k++) {
        float hv = fmaxf(hh[k], 0.f);
        o0 += hv * sW2[k * 2 + 0];
        o1 += hv * sW2[k * 2 + 1];
    }
    out[(size_t)row * 2 + 0] = o0;
    out[(size_t)row * 2 + 1] = o1;
}

// ---------------------------------------------------------------------------
// launch
// ---------------------------------------------------------------------------
extern "C" void kernel_launch(void* const* d_in, const int* in_sizes, int n_in,
                              void* d_out, int out_size) {
    const float* x_ind = (const float*)d_in[0];
    const float* x_com = (const float*)d_in[1];
    const float* x_tru = (const float*)d_in[2];
    const int*   ei    = (const int*)d_in[3];
    const float* W_ind = (const float*)d_in[4];
    const float* b_ind = (const float*)d_in[5];
    const float* W_com = (const float*)d_in[6];
    const float* b_com = (const float*)d_in[7];
    const float* W_tru = (const float*)d_in[8];
    const float* b_tru = (const float*)d_in[9];
    const float* W1l = (const float*)d_in[10];
    const float* W1r = (const float*)d_in[11];
    const float* b1  = (const float*)d_in[12];
    const float* W2l = (const float*)d_in[13];
    const float* W2r = (const float*)d_in[14];
    const float* b2  = (const float*)d_in[15];
    const float* Wc1 = (const float*)d_in[16];
    const float* bc1 = (const float*)d_in[17];
    const float* Wc2 = (const float*)d_in[18];
    const float* bc2 = (const float*)d_in[19];

    int n_ind = in_sizes[0] / 32;
    int n_com = in_sizes[1] / 48;
    int n_tru = in_sizes[2] / 24;
    int N = n_ind + n_com + n_tru;
    int E = in_sizes[3] / 2;
    const int* src = ei;
    const int* dst = ei + E;

    float *gx, *gy, *gagg, *gcnt;
    cudaGetSymbolAddress((void**)&gx, g_x);
    cudaGetSymbolAddress((void**)&gy, g_y);
    cudaGetSymbolAddress((void**)&gagg, g_agg);
    cudaGetSymbolAddress((void**)&gcnt, g_cnt);

    // ---- encoders -> g_x
    encode_kernel<32><<<(n_ind + 127) / 128, 128>>>(x_ind, W_ind, b_ind, gx, n_ind);
    encode_kernel<48><<<(n_com + 127) / 128, 128>>>(x_com, W_com, b_com,
                                                    gx + (size_t)n_ind * HD, n_com);
    encode_kernel<24><<<(n_tru + 127) / 128, 128>>>(x_tru, W_tru, b_tru,
                                                    gx + (size_t)(n_ind + n_com) * HD, n_tru);

    // ---- in-degree (shared by both layers)
    long long cnt4 = N / 4;
    zero_kernel<<<(int)((cnt4 + 255) / 256), 256>>>(gcnt, cnt4);
    degree_kernel<<<(E + 255) / 256, 256>>>(dst, gcnt, E);

    long long n4 = (long long)N * HD / 4;
    long long tot = (long long)E * 16;

    // ---- SAGE layer 1: g_x -> g_y
    zero_kernel<<<(int)((n4 + 255) / 256), 256>>>(gagg, n4);
    scatter_kernel<<<(int)((tot + 255) / 256), 256>>>(gx, src, dst, gagg, E);
    sage_combine_kernel<<<(N + 127) / 128, 128>>>(gx, gagg, gcnt, W1l, W1r, b1, gy, N);

    // ---- SAGE layer 2: g_y -> g_x (reuse)
    zero_kernel<<<(int)((n4 + 255) / 256), 256>>>(gagg, n4);
    scatter_kernel<<<(int)((tot + 255) / 256), 256>>>(gy, src, dst, gagg, E);
    sage_combine_kernel<<<(N + 127) / 128, 128>>>(gy, gagg, gcnt, W2l, W2r, b2, gx, N);

    // ---- classifier -> d_out
    classify_kernel<<<(N + 127) / 128, 128>>>(gx, Wc1, bc1, Wc2, bc2, (float*)d_out, N);
}

// round 2
// speedup vs baseline: 1.3561x; 1.3561x over previous
#include <cuda_runtime.h>
#include <cstdint>

#define HD 64
#define NMAX 300000
#define EMAX 4800000

// Scratch — device globals (no cudaMalloc allowed).
__device__ float g_x[(size_t)NMAX * HD];    // encoded / layer-out features
__device__ float g_y[(size_t)NMAX * HD];    // layer-1 output
__device__ float g_agg[(size_t)NMAX * HD];  // neighbor-mean buffer
__device__ int   g_deg[NMAX];               // in-degree
__device__ int   g_excl[NMAX];              // block-local exclusive scan
__device__ int   g_off[NMAX + 1];           // CSR offsets
__device__ int   g_cur[NMAX];               // bucket cursors
__device__ int   g_bsum[512];               // per-block sums for scan
__device__ int   g_nbr[EMAX];               // CSR neighbor (src) ids

// ---------------------------------------------------------------------------
// zero fill (16B granularity)
// ---------------------------------------------------------------------------
__global__ void zero_kernel(float4* __restrict__ p, int n4) {
    int i = blockIdx.x * blockDim.x + threadIdx.x;
    if (i < n4) p[i] = make_float4(0.f, 0.f, 0.f, 0.f);
}

// ---------------------------------------------------------------------------
// in-degree histogram
// ---------------------------------------------------------------------------
__global__ void degree_kernel(const int* __restrict__ dst, int* __restrict__ deg, int E) {
    int i = blockIdx.x * blockDim.x + threadIdx.x;
    if (i < E) atomicAdd(deg + __ldg(dst + i), 1);
}

// ---------------------------------------------------------------------------
// prefix scan (3 kernels): 1024 elems/block
// ---------------------------------------------------------------------------
__global__ __launch_bounds__(256) void scan1_kernel(const int* __restrict__ deg,
                                                    int* __restrict__ excl,
                                                    int* __restrict__ bsum, int n) {
    __shared__ int wsum[8];
    int t = threadIdx.x;
    int base = blockIdx.x * 1024 + t * 4;
    int v[4];
#pragma unroll
    for (int k = 0; k < 4; k++) v[k] = (base + k < n) ? deg[base + k] : 0;
    int tsum = v[0] + v[1] + v[2] + v[3];
    int lane = t & 31, w = t >> 5;
    int x = tsum;
#pragma unroll
    for (int o = 1; o < 32; o <<= 1) {
        int y = __shfl_up_sync(~0u, x, o);
        if (lane >= o) x += y;
    }
    if (lane == 31) wsum[w] = x;
    __syncthreads();
    if (t < 8) {
        int y = wsum[t];
#pragma unroll
        for (int o = 1; o < 8; o <<= 1) {
            int z = __shfl_up_sync(0xff, y, o);
            if (t >= o) y += z;
        }
        wsum[t] = y;
    }
    __syncthreads();
    int run = (w > 0 ? wsum[w - 1] : 0) + x - tsum;  // exclusive over threads
#pragma unroll
    for (int k = 0; k < 4; k++) {
        if (base + k < n) excl[base + k] = run;
        run += v[k];
    }
    if (t == 0) bsum[blockIdx.x] = wsum[7];
}

__global__ __launch_bounds__(512) void scan2_kernel(int* __restrict__ bsum, int nb) {
    __shared__ int wsum[16];
    int t = threadIdx.x;
    int v = (t < nb) ? bsum[t] : 0;
    int lane = t & 31, w = t >> 5;
    int x = v;
#pragma unroll
    for (int o = 1; o < 32; o <<= 1) {
        int y = __shfl_up_sync(~0u, x, o);
        if (lane >= o) x += y;
    }
    if (lane == 31) wsum[w] = x;
    __syncthreads();
    if (t < 16) {
        int y = wsum[t];
#pragma unroll
        for (int o = 1; o < 16; o <<= 1) {
            int z = __shfl_up_sync(0xffff, y, o);
            if (t >= o) y += z;
        }
        wsum[t] = y;
    }
    __syncthreads();
    int excl = (w > 0 ? wsum[w - 1] : 0) + x - v;
    if (t < nb) bsum[t] = excl;
}

__global__ void scan3_kernel(const int* __restrict__ excl, const int* __restrict__ bsum,
                             int* __restrict__ off, int* __restrict__ cur, int n, int E) {
    int i = blockIdx.x * blockDim.x + threadIdx.x;
    if (i < n) {
        int o = excl[i] + bsum[i >> 10];
        off[i] = o;
        cur[i] = o;
    }
    if (i == 0) off[n] = E;
}

// ---------------------------------------------------------------------------
// bucket permute: nbr sorted by dst
// ---------------------------------------------------------------------------
__global__ void bucket_kernel(const int* __restrict__ src, const int* __restrict__ dst,
                              int* __restrict__ cur, int* __restrict__ nbr, int E) {
    int i = blockIdx.x * blockDim.x + threadIdx.x;
    if (i < E) {
        int p = atomicAdd(cur + __ldg(dst + i), 1);
        nbr[p] = __ldg(src + i);
    }
}

// ---------------------------------------------------------------------------
// gather aggregation: mean over neighbors, one warp per node
// lane owns 2 columns (float2); 32 lanes x 8B = one coalesced 256B row
// ---------------------------------------------------------------------------
__global__ __launch_bounds__(256) void agg_kernel(const float* __restrict__ x,
                                                  const int* __restrict__ off,
                                                  const int* __restrict__ nbr,
                                                  float* __restrict__ agg, int N) {
    int warp = (blockIdx.x * blockDim.x + threadIdx.x) >> 5;
    if (warp >= N) return;
    int lane = threadIdx.x & 31;
    int s0 = __ldg(off + warp), s1 = __ldg(off + warp + 1);
    float ax = 0.f, ay = 0.f;
    int j = s0;
    for (; j + 32 <= s1; j += 32) {
        int myid = __ldg(nbr + j + lane);
#pragma unroll
        for (int k = 0; k < 32; k++) {
            int s = __shfl_sync(~0u, myid, k);
            float2 v = *reinterpret_cast<const float2*>(x + (size_t)s * HD + lane * 2);
            ax += v.x;
            ay += v.y;
        }
    }
    if (j < s1) {
        int cnt = s1 - j;
        int myid = (lane < cnt) ? __ldg(nbr + j + lane) : 0;
        for (int k = 0; k < cnt; k++) {
            int s = __shfl_sync(~0u, myid, k);
            float2 v = *reinterpret_cast<const float2*>(x + (size_t)s * HD + lane * 2);
            ax += v.x;
            ay += v.y;
        }
    }
    int deg = s1 - s0;
    float inv = 1.0f / (float)max(deg, 1);
    float2 o;
    o.x = ax * inv;
    o.y = ay * inv;
    *reinterpret_cast<float2*>(agg + (size_t)warp * HD + lane * 2) = o;
}

// ---------------------------------------------------------------------------
// per-type encoder: out[row] = x[row] @ W[FIN,64] + b    (row per thread)
// ---------------------------------------------------------------------------
template <int FIN>
__global__ __launch_bounds__(128) void encode_kernel(
    const float* __restrict__ x, const float* __restrict__ W,
    const float* __restrict__ b, float* __restrict__ out, int n) {
    __shared__ float sW[FIN * HD];
    __shared__ float sb[HD];
    for (int i = threadIdx.x; i < FIN * HD; i += 128) sW[i] = W[i];
    if (threadIdx.x < HD) sb[threadIdx.x] = b[threadIdx.x];
    __syncthreads();
    int row = blockIdx.x * 128 + threadIdx.x;
    if (row >= n) return;

    float4 acc[16];
#pragma unroll
    for (int c = 0; c < 16; c++) acc[c] = reinterpret_cast<const float4*>(sb)[c];

    const float4* xr = reinterpret_cast<const float4*>(x + (size_t)row * FIN);
#pragma unroll 1
    for (int kc = 0; kc < FIN / 4; kc++) {
        float4 xv = xr[kc];
        float xk[4] = {xv.x, xv.y, xv.z, xv.w};
#pragma unroll
        for (int kk = 0; kk < 4; kk++) {
            const float4* w = reinterpret_cast<const float4*>(sW + (kc * 4 + kk) * HD);
#pragma unroll
            for (int c = 0; c < 16; c++) {
                float4 wv = w[c];
                acc[c].x += xk[kk] * wv.x;
                acc[c].y += xk[kk] * wv.y;
                acc[c].z += xk[kk] * wv.z;
                acc[c].w += xk[kk] * wv.w;
            }
        }
    }
    float4* o = reinterpret_cast<float4*>(out + (size_t)row * HD);
#pragma unroll
    for (int c = 0; c < 16; c++) o[c] = acc[c];
}

// ---------------------------------------------------------------------------
// SAGE combine: out = relu( mean @ Wl + x @ Wr + b )   (mean precomputed)
// ---------------------------------------------------------------------------
__global__ __launch_bounds__(128) void sage_combine_kernel(
    const float* __restrict__ x, const float* __restrict__ mean,
    const float* __restrict__ Wl, const float* __restrict__ Wr,
    const float* __restrict__ b, float* __restrict__ out, int n) {
    __shared__ float sWl[HD * HD];
    __shared__ float sWr[HD * HD];
    __shared__ float sb[HD];
    for (int i = threadIdx.x; i < HD * HD; i += 128) {
        sWl[i] = Wl[i];
        sWr[i] = Wr[i];
    }
    if (threadIdx.x < HD) sb[threadIdx.x] = b[threadIdx.x];
    __syncthreads();
    int row = blockIdx.x * 128 + threadIdx.x;
    if (row >= n) return;

    float4 acc[16];
#pragma unroll
    for (int c = 0; c < 16; c++) acc[c] = reinterpret_cast<const float4*>(sb)[c];

    const float4* xr = reinterpret_cast<const float4*>(x + (size_t)row * HD);
    const float4* ar = reinterpret_cast<const float4*>(mean + (size_t)row * HD);
#pragma unroll 1
    for (int kc = 0; kc < 16; kc++) {
        float4 xv = xr[kc];
        float4 av = ar[kc];
        float xk[4] = {xv.x, xv.y, xv.z, xv.w};
        float mk[4] = {av.x, av.y, av.z, av.w};
#pragma unroll
        for (int kk = 0; kk < 4; kk++) {
            int k = kc * 4 + kk;
            const float4* wl = reinterpret_cast<const float4*>(sWl + k * HD);
            const float4* wr = reinterpret_cast<const float4*>(sWr + k * HD);
#pragma unroll
            for (int c = 0; c < 16; c++) {
                float4 l = wl[c];
                float4 r = wr[c];
                acc[c].x += mk[kk] * l.x + xk[kk] * r.x;
                acc[c].y += mk[kk] * l.y + xk[kk] * r.y;
                acc[c].z += mk[kk] * l.z + xk[kk] * r.z;
                acc[c].w += mk[kk] * l.w + xk[kk] * r.w;
            }
        }
    }
    float4* o = reinterpret_cast<float4*>(out + (size_t)row * HD);
#pragma unroll
    for (int c = 0; c < 16; c++) {
        float4 v = acc[c];
        v.x = fmaxf(v.x, 0.f);
        v.y = fmaxf(v.y, 0.f);
        v.z = fmaxf(v.z, 0.f);
        v.w = fmaxf(v.w, 0.f);
        o[c] = v;
    }
}

// ---------------------------------------------------------------------------
// classifier: out = relu(x @ Wc1[64,32] + bc1) @ Wc2[32,2] + bc2
// ---------------------------------------------------------------------------
__global__ __launch_bounds__(128) void classify_kernel(
    const float* __restrict__ x,
    const float* __restrict__ Wc1, const float* __restrict__ bc1,
    const float* __restrict__ Wc2, const float* __restrict__ bc2,
    float* __restrict__ out, int n) {
    __shared__ float sW1[HD * 32];
    __shared__ float sW2[32 * 2];
    __shared__ float sb1[32];
    __shared__ float sb2[2];
    for (int i = threadIdx.x; i < HD * 32; i += 128) sW1[i] = Wc1[i];
    if (threadIdx.x < 64) sW2[threadIdx.x] = Wc2[threadIdx.x];
    if (threadIdx.x < 32) sb1[threadIdx.x] = bc1[threadIdx.x];
    if (threadIdx.x < 2) sb2[threadIdx.x] = bc2[threadIdx.x];
    __syncthreads();
    int row = blockIdx.x * 128 + threadIdx.x;
    if (row >= n) return;

    float4 h[8];
#pragma unroll
    for (int c = 0; c < 8; c++) h[c] = reinterpret_cast<const float4*>(sb1)[c];

    const float4* xr = reinterpret_cast<const float4*>(x + (size_t)row * HD);
#pragma unroll 1
    for (int kc = 0; kc < 16; kc++) {
        float4 xv = xr[kc];
        float xk[4] = {xv.x, xv.y, xv.z, xv.w};
#pragma unroll
        for (int kk = 0; kk < 4; kk++) {
            const float4* w = reinterpret_cast<const float4*>(sW1 + (kc * 4 + kk) * 32);
#pragma unroll
            for (int c = 0; c < 8; c++) {
                float4 wv = w[c];
                h[c].x += xk[kk] * wv.x;
                h[c].y += xk[kk] * wv.y;
                h[c].z += xk[kk] * wv.z;
                h[c].w += xk[kk] * wv.w;
            }
        }
    }
    float o0 = sb2[0], o1 = sb2[1];
    float* hh = reinterpret_cast<float*>(h);
#pragma unroll
    for (int k = 0; k < 32; k++) {
        float hv = fmaxf(hh[k], 0.f);
        o0 += hv * sW2[k * 2 + 0];
        o1 += hv * sW2[k * 2 + 1];
    }
    out[(size_t)row * 2 + 0] = o0;
    out[(size_t)row * 2 + 1] = o1;
}

// ---------------------------------------------------------------------------
// launch
// ---------------------------------------------------------------------------
extern "C" void kernel_launch(void* const* d_in, const int* in_sizes, int n_in,
                              void* d_out, int out_size) {
    const float* x_ind = (const float*)d_in[0];
    const float* x_com = (const float*)d_in[1];
    const float* x_tru = (const float*)d_in[2];
    const int*   ei    = (const int*)d_in[3];
    const float* W_ind = (const float*)d_in[4];
    const float* b_ind = (const float*)d_in[5];
    const float* W_com = (const float*)d_in[6];
    const float* b_com = (const float*)d_in[7];
    const float* W_tru = (const float*)d_in[8];
    const float* b_tru = (const float*)d_in[9];
    const float* W1l = (const float*)d_in[10];
    const float* W1r = (const float*)d_in[11];
    const float* b1  = (const float*)d_in[12];
    const float* W2l = (const float*)d_in[13];
    const float* W2r = (const float*)d_in[14];
    const float* b2  = (const float*)d_in[15];
    const float* Wc1 = (const float*)d_in[16];
    const float* bc1 = (const float*)d_in[17];
    const float* Wc2 = (const float*)d_in[18];
    const float* bc2 = (const float*)d_in[19];

    int n_ind = in_sizes[0] / 32;
    int n_com = in_sizes[1] / 48;
    int n_tru = in_sizes[2] / 24;
    int N = n_ind + n_com + n_tru;
    int E = in_sizes[3] / 2;
    const int* src = ei;
    const int* dst = ei + E;

    float *gx, *gy, *gagg;
    int *gdeg, *gexcl, *goff, *gcur, *gbsum, *gnbr;
    cudaGetSymbolAddress((void**)&gx, g_x);
    cudaGetSymbolAddress((void**)&gy, g_y);
    cudaGetSymbolAddress((void**)&gagg, g_agg);
    cudaGetSymbolAddress((void**)&gdeg, g_deg);
    cudaGetSymbolAddress((void**)&gexcl, g_excl);
    cudaGetSymbolAddress((void**)&goff, g_off);
    cudaGetSymbolAddress((void**)&gcur, g_cur);
    cudaGetSymbolAddress((void**)&gbsum, g_bsum);
    cudaGetSymbolAddress((void**)&gnbr, g_nbr);

    // ---- encoders -> g_x (overlap with CSR build on same stream is fine;
    //      they're independent but serialization cost is small)
    encode_kernel<32><<<(n_ind + 127) / 128, 128>>>(x_ind, W_ind, b_ind, gx, n_ind);
    encode_kernel<48><<<(n_com + 127) / 128, 128>>>(x_com, W_com, b_com,
                                                    gx + (size_t)n_ind * HD, n_com);
    encode_kernel<24><<<(n_tru + 127) / 128, 128>>>(x_tru, W_tru, b_tru,
                                                    gx + (size_t)(n_ind + n_com) * HD, n_tru);

    // ---- CSR build
    int nInt4 = (N + 3) / 4;
    zero_kernel<<<(nInt4 + 255) / 256, 256>>>((float4*)gdeg, nInt4);
    degree_kernel<<<(E + 255) / 256, 256>>>(dst, gdeg, E);
    int nb = (N + 1023) / 1024;
    scan1_kernel<<<nb, 256>>>(gdeg, gexcl, gbsum, N);
    scan2_kernel<<<1, 512>>>(gbsum, nb);
    scan3_kernel<<<(N + 255) / 256, 256>>>(gexcl, gbsum, goff, gcur, N, E);
    bucket_kernel<<<(E + 255) / 256, 256>>>(src, dst, gcur, gnbr, E);

    // ---- SAGE layer 1: g_x -> g_y
    agg_kernel<<<(N * 32 + 255) / 256, 256>>>(gx, goff, gnbr, gagg, N);
    sage_combine_kernel<<<(N + 127) / 128, 128>>>(gx, gagg, W1l, W1r, b1, gy, N);

    // ---- SAGE layer 2: g_y -> g_x
    agg_kernel<<<(N * 32 + 255) / 256, 256>>>(gy, goff, gnbr, gagg, N);
    sage_combine_kernel<<<(N + 127) / 128, 128>>>(gy, gagg, W2l, W2r, b2, gx, N);

    // ---- classifier -> d_out
    classify_kernel<<<(N + 127) / 128, 128>>>(gx, Wc1, bc1, Wc2, bc2, (float*)d_out, N);
}

// round 3
// speedup vs baseline: 1.4120x; 1.0413x over previous
#include <cuda_runtime.h>
#include <cstdint>

#define HD 64
#define NMAX 300000
#define EMAX 4800000

// Scratch — device globals (no cudaMalloc allowed).
__device__ float g_x[(size_t)NMAX * HD];    // encoded / layer-out features
__device__ float g_y[(size_t)NMAX * HD];    // layer-1 output
__device__ float g_agg[(size_t)NMAX * HD];  // neighbor-mean buffer
__device__ int   g_deg[NMAX];               // in-degree
__device__ int   g_excl[NMAX];              // block-local exclusive scan
__device__ int   g_off[NMAX + 1];           // CSR offsets
__device__ int   g_cur[NMAX];               // bucket cursors
__device__ int   g_bsum[512];               // per-block sums for scan
__device__ int   g_nbr[EMAX];               // CSR neighbor (src) ids

// ---------------------------------------------------------------------------
// packed f32x2 helpers (sm_103a FFMA2 — only reachable via PTX)
// ---------------------------------------------------------------------------
__device__ __forceinline__ unsigned long long fma2(unsigned long long a,
                                                   unsigned long long b,
                                                   unsigned long long c) {
    unsigned long long d;
    asm("fma.rn.f32x2 %0, %1, %2, %3;" : "=l"(d) : "l"(a), "l"(b), "l"(c));
    return d;
}
__device__ __forceinline__ unsigned long long pack2(float x) {
    unsigned long long d;
    asm("mov.b64 %0, {%1, %1};" : "=l"(d) : "f"(x));
    return d;
}
__device__ __forceinline__ void unpack2(unsigned long long v, float& lo, float& hi) {
    asm("mov.b64 {%0, %1}, %2;" : "=f"(lo), "=f"(hi) : "l"(v));
}

// ---------------------------------------------------------------------------
// zero fill (16B granularity)
// ---------------------------------------------------------------------------
__global__ void zero_kernel(float4* __restrict__ p, int n4) {
    int i = blockIdx.x * blockDim.x + threadIdx.x;
    if (i < n4) p[i] = make_float4(0.f, 0.f, 0.f, 0.f);
}

// ---------------------------------------------------------------------------
// in-degree histogram
// ---------------------------------------------------------------------------
__global__ void degree_kernel(const int* __restrict__ dst, int* __restrict__ deg, int E) {
    int i = blockIdx.x * blockDim.x + threadIdx.x;
    if (i < E) atomicAdd(deg + __ldg(dst + i), 1);
}

// ---------------------------------------------------------------------------
// prefix scan (3 kernels): 1024 elems/block
// ---------------------------------------------------------------------------
__global__ __launch_bounds__(256) void scan1_kernel(const int* __restrict__ deg,
                                                    int* __restrict__ excl,
                                                    int* __restrict__ bsum, int n) {
    __shared__ int wsum[8];
    int t = threadIdx.x;
    int base = blockIdx.x * 1024 + t * 4;
    int v[4];
#pragma unroll
    for (int k = 0; k < 4; k++) v[k] = (base + k < n) ? deg[base + k] : 0;
    int tsum = v[0] + v[1] + v[2] + v[3];
    int lane = t & 31, w = t >> 5;
    int x = tsum;
#pragma unroll
    for (int o = 1; o < 32; o <<= 1) {
        int y = __shfl_up_sync(~0u, x, o);
        if (lane >= o) x += y;
    }
    if (lane == 31) wsum[w] = x;
    __syncthreads();
    if (t < 8) {
        int y = wsum[t];
#pragma unroll
        for (int o = 1; o < 8; o <<= 1) {
            int z = __shfl_up_sync(0xff, y, o);
            if (t >= o) y += z;
        }
        wsum[t] = y;
    }
    __syncthreads();
    int run = (w > 0 ? wsum[w - 1] : 0) + x - tsum;  // exclusive over threads
#pragma unroll
    for (int k = 0; k < 4; k++) {
        if (base + k < n) excl[base + k] = run;
        run += v[k];
    }
    if (t == 0) bsum[blockIdx.x] = wsum[7];
}

__global__ __launch_bounds__(512) void scan2_kernel(int* __restrict__ bsum, int nb) {
    __shared__ int wsum[16];
    int t = threadIdx.x;
    int v = (t < nb) ? bsum[t] : 0;
    int lane = t & 31, w = t >> 5;
    int x = v;
#pragma unroll
    for (int o = 1; o < 32; o <<= 1) {
        int y = __shfl_up_sync(~0u, x, o);
        if (lane >= o) x += y;
    }
    if (lane == 31) wsum[w] = x;
    __syncthreads();
    if (t < 16) {
        int y = wsum[t];
#pragma unroll
        for (int o = 1; o < 16; o <<= 1) {
            int z = __shfl_up_sync(0xffff, y, o);
            if (t >= o) y += z;
        }
        wsum[t] = y;
    }
    __syncthreads();
    int excl = (w > 0 ? wsum[w - 1] : 0) + x - v;
    if (t < nb) bsum[t] = excl;
}

__global__ void scan3_kernel(const int* __restrict__ excl, const int* __restrict__ bsum,
                             int* __restrict__ off, int* __restrict__ cur, int n, int E) {
    int i = blockIdx.x * blockDim.x + threadIdx.x;
    if (i < n) {
        int o = excl[i] + bsum[i >> 10];
        off[i] = o;
        cur[i] = o;
    }
    if (i == 0) off[n] = E;
}

// ---------------------------------------------------------------------------
// bucket permute: nbr sorted by dst
// ---------------------------------------------------------------------------
__global__ void bucket_kernel(const int* __restrict__ src, const int* __restrict__ dst,
                              int* __restrict__ cur, int* __restrict__ nbr, int E) {
    int i = blockIdx.x * blockDim.x + threadIdx.x;
    if (i < E) {
        int p = atomicAdd(cur + __ldg(dst + i), 1);
        nbr[p] = __ldg(src + i);
    }
}

// ---------------------------------------------------------------------------
// gather aggregation: mean over neighbors, one warp per node
// lane owns 2 columns (float2); 32 lanes x 8B = one coalesced 256B row
// ---------------------------------------------------------------------------
__global__ __launch_bounds__(256) void agg_kernel(const float* __restrict__ x,
                                                  const int* __restrict__ off,
                                                  const int* __restrict__ nbr,
                                                  float* __restrict__ agg, int N) {
    int warp = (blockIdx.x * blockDim.x + threadIdx.x) >> 5;
    if (warp >= N) return;
    int lane = threadIdx.x & 31;
    int s0 = __ldg(off + warp), s1 = __ldg(off + warp + 1);
    float ax = 0.f, ay = 0.f;
    int j = s0;
    for (; j + 32 <= s1; j += 32) {
        int myid = __ldg(nbr + j + lane);
#pragma unroll
        for (int k = 0; k < 32; k++) {
            int s = __shfl_sync(~0u, myid, k);
            float2 v = *reinterpret_cast<const float2*>(x + (size_t)s * HD + lane * 2);
            ax += v.x;
            ay += v.y;
        }
    }
    if (j < s1) {
        int cnt = s1 - j;
        int myid = (lane < cnt) ? __ldg(nbr + j + lane) : 0;
        for (int k = 0; k < cnt; k++) {
            int s = __shfl_sync(~0u, myid, k);
            float2 v = *reinterpret_cast<const float2*>(x + (size_t)s * HD + lane * 2);
            ax += v.x;
            ay += v.y;
        }
    }
    int deg = s1 - s0;
    float inv = 1.0f / (float)max(deg, 1);
    float2 o;
    o.x = ax * inv;
    o.y = ay * inv;
    *reinterpret_cast<float2*>(agg + (size_t)warp * HD + lane * 2) = o;
}

// ---------------------------------------------------------------------------
// per-type encoder: out[row] = x[row] @ W[FIN,64] + b    (row per thread, f32x2)
// ---------------------------------------------------------------------------
template <int FIN>
__global__ __launch_bounds__(128) void encode_kernel(
    const float* __restrict__ x, const float* __restrict__ W,
    const float* __restrict__ b, float* __restrict__ out, int n) {
    __shared__ float sW[FIN * HD];
    __shared__ float sb[HD];
    for (int i = threadIdx.x; i < FIN * HD; i += 128) sW[i] = W[i];
    if (threadIdx.x < HD) sb[threadIdx.x] = b[threadIdx.x];
    __syncthreads();
    int row = blockIdx.x * 128 + threadIdx.x;
    if (row >= n) return;

    unsigned long long acc[32];
#pragma unroll
    for (int c = 0; c < 32; c++) acc[c] = reinterpret_cast<const unsigned long long*>(sb)[c];

    const float4* xr = reinterpret_cast<const float4*>(x + (size_t)row * FIN);
#pragma unroll 1
    for (int kc = 0; kc < FIN / 4; kc++) {
        float4 xv = xr[kc];
        float xk[4] = {xv.x, xv.y, xv.z, xv.w};
#pragma unroll
        for (int kk = 0; kk < 4; kk++) {
            unsigned long long xk2 = pack2(xk[kk]);
            const ulonglong2* w =
                reinterpret_cast<const ulonglong2*>(sW + (kc * 4 + kk) * HD);
#pragma unroll
            for (int c = 0; c < 16; c++) {
                ulonglong2 wv = w[c];
                acc[c * 2 + 0] = fma2(xk2, wv.x, acc[c * 2 + 0]);
                acc[c * 2 + 1] = fma2(xk2, wv.y, acc[c * 2 + 1]);
            }
        }
    }
    float4* o = reinterpret_cast<float4*>(out + (size_t)row * HD);
#pragma unroll
    for (int c = 0; c < 16; c++) {
        float4 v;
        unpack2(acc[c * 2 + 0], v.x, v.y);
        unpack2(acc[c * 2 + 1], v.z, v.w);
        o[c] = v;
    }
}

// ---------------------------------------------------------------------------
// SAGE combine: out = relu( mean @ Wl + x @ Wr + b )   (f32x2 inner loop)
// ---------------------------------------------------------------------------
__global__ __launch_bounds__(128) void sage_combine_kernel(
    const float* __restrict__ x, const float* __restrict__ mean,
    const float* __restrict__ Wl, const float* __restrict__ Wr,
    const float* __restrict__ b, float* __restrict__ out, int n) {
    __shared__ float sWl[HD * HD];
    __shared__ float sWr[HD * HD];
    __shared__ float sb[HD];
    for (int i = threadIdx.x; i < HD * HD; i += 128) {
        sWl[i] = Wl[i];
        sWr[i] = Wr[i];
    }
    if (threadIdx.x < HD) sb[threadIdx.x] = b[threadIdx.x];
    __syncthreads();
    int row = blockIdx.x * 128 + threadIdx.x;
    if (row >= n) return;

    unsigned long long acc[32];
#pragma unroll
    for (int c = 0; c < 32; c++) acc[c] = reinterpret_cast<const unsigned long long*>(sb)[c];

    const float4* xr = reinterpret_cast<const float4*>(x + (size_t)row * HD);
    const float4* ar = reinterpret_cast<const float4*>(mean + (size_t)row * HD);
#pragma unroll 1
    for (int kc = 0; kc < 16; kc++) {
        float4 xv = xr[kc];
        float4 av = ar[kc];
        float xk[4] = {xv.x, xv.y, xv.z, xv.w};
        float mk[4] = {av.x, av.y, av.z, av.w};
#pragma unroll
        for (int kk = 0; kk < 4; kk++) {
            int k = kc * 4 + kk;
            unsigned long long xk2 = pack2(xk[kk]);
            unsigned long long mk2 = pack2(mk[kk]);
            const ulonglong2* wl = reinterpret_cast<const ulonglong2*>(sWl + k * HD);
            const ulonglong2* wr = reinterpret_cast<const ulonglong2*>(sWr + k * HD);
#pragma unroll
            for (int c = 0; c < 16; c++) {
                ulonglong2 l = wl[c];
                ulonglong2 r = wr[c];
                acc[c * 2 + 0] = fma2(mk2, l.x, acc[c * 2 + 0]);
                acc[c * 2 + 0] = fma2(xk2, r.x, acc[c * 2 + 0]);
                acc[c * 2 + 1] = fma2(mk2, l.y, acc[c * 2 + 1]);
                acc[c * 2 + 1] = fma2(xk2, r.y, acc[c * 2 + 1]);
            }
        }
    }
    float4* o = reinterpret_cast<float4*>(out + (size_t)row * HD);
#pragma unroll
    for (int c = 0; c < 16; c++) {
        float4 v;
        unpack2(acc[c * 2 + 0], v.x, v.y);
        unpack2(acc[c * 2 + 1], v.z, v.w);
        v.x = fmaxf(v.x, 0.f);
        v.y = fmaxf(v.y, 0.f);
        v.z = fmaxf(v.z, 0.f);
        v.w = fmaxf(v.w, 0.f);
        o[c] = v;
    }
}

// ---------------------------------------------------------------------------
// classifier: out = relu(x @ Wc1[64,32] + bc1) @ Wc2[32,2] + bc2   (f32x2)
// ---------------------------------------------------------------------------
__global__ __launch_bounds__(128) void classify_kernel(
    const float* __restrict__ x,
    const float* __restrict__ Wc1, const float* __restrict__ bc1,
    const float* __restrict__ Wc2, const float* __restrict__ bc2,
    float* __restrict__ out, int n) {
    __shared__ float sW1[HD * 32];
    __shared__ float sW2[32 * 2];
    __shared__ float sb1[32];
    __shared__ float sb2[2];
    for (int i = threadIdx.x; i < HD * 32; i += 128) sW1[i] = Wc1[i];
    if (threadIdx.x < 64) sW2[threadIdx.x] = Wc2[threadIdx.x];
    if (threadIdx.x < 32) sb1[threadIdx.x] = bc1[threadIdx.x];
    if (threadIdx.x < 2) sb2[threadIdx.x] = bc2[threadIdx.x];
    __syncthreads();
    int row = blockIdx.x * 128 + threadIdx.x;
    if (row >= n) return;

    unsigned long long h[16];
#pragma unroll
    for (int c = 0; c < 16; c++) h[c] = reinterpret_cast<const unsigned long long*>(sb1)[c];

    const float4* xr = reinterpret_cast<const float4*>(x + (size_t)row * HD);
#pragma unroll 1
    for (int kc = 0; kc < 16; kc++) {
        float4 xv = xr[kc];
        float xk[4] = {xv.x, xv.y, xv.z, xv.w};
#pragma unroll
        for (int kk = 0; kk < 4; kk++) {
            unsigned long long xk2 = pack2(xk[kk]);
            const ulonglong2* w =
                reinterpret_cast<const ulonglong2*>(sW1 + (kc * 4 + kk) * 32);
#pragma unroll
            for (int c = 0; c < 8; c++) {
                ulonglong2 wv = w[c];
                h[c * 2 + 0] = fma2(xk2, wv.x, h[c * 2 + 0]);
                h[c * 2 + 1] = fma2(xk2, wv.y, h[c * 2 + 1]);
            }
        }
    }
    float o0 = sb2[0], o1 = sb2[1];
#pragma unroll
    for (int c = 0; c < 16; c++) {
        float a, bb;
        unpack2(h[c], a, bb);
        a = fmaxf(a, 0.f);
        bb = fmaxf(bb, 0.f);
        o0 += a * sW2[(c * 2 + 0) * 2 + 0] + bb * sW2[(c * 2 + 1) * 2 + 0];
        o1 += a * sW2[(c * 2 + 0) * 2 + 1] + bb * sW2[(c * 2 + 1) * 2 + 1];
    }
    out[(size_t)row * 2 + 0] = o0;
    out[(size_t)row * 2 + 1] = o1;
}

// ---------------------------------------------------------------------------
// launch
// ---------------------------------------------------------------------------
extern "C" void kernel_launch(void* const* d_in, const int* in_sizes, int n_in,
                              void* d_out, int out_size) {
    const float* x_ind = (const float*)d_in[0];
    const float* x_com = (const float*)d_in[1];
    const float* x_tru = (const float*)d_in[2];
    const int*   ei    = (const int*)d_in[3];
    const float* W_ind = (const float*)d_in[4];
    const float* b_ind = (const float*)d_in[5];
    const float* W_com = (const float*)d_in[6];
    const float* b_com = (const float*)d_in[7];
    const float* W_tru = (const float*)d_in[8];
    const float* b_tru = (const float*)d_in[9];
    const float* W1l = (const float*)d_in[10];
    const float* W1r = (const float*)d_in[11];
    const float* b1  = (const float*)d_in[12];
    const float* W2l = (const float*)d_in[13];
    const float* W2r = (const float*)d_in[14];
    const float* b2  = (const float*)d_in[15];
    const float* Wc1 = (const float*)d_in[16];
    const float* bc1 = (const float*)d_in[17];
    const float* Wc2 = (const float*)d_in[18];
    const float* bc2 = (const float*)d_in[19];

    int n_ind = in_sizes[0] / 32;
    int n_com = in_sizes[1] / 48;
    int n_tru = in_sizes[2] / 24;
    int N = n_ind + n_com + n_tru;
    int E = in_sizes[3] / 2;
    const int* src = ei;
    const int* dst = ei + E;

    float *gx, *gy, *gagg;
    int *gdeg, *gexcl, *goff, *gcur, *gbsum, *gnbr;
    cudaGetSymbolAddress((void**)&gx, g_x);
    cudaGetSymbolAddress((void**)&gy, g_y);
    cudaGetSymbolAddress((void**)&gagg, g_agg);
    cudaGetSymbolAddress((void**)&gdeg, g_deg);
    cudaGetSymbolAddress((void**)&gexcl, g_excl);
    cudaGetSymbolAddress((void**)&goff, g_off);
    cudaGetSymbolAddress((void**)&gcur, g_cur);
    cudaGetSymbolAddress((void**)&gbsum, g_bsum);
    cudaGetSymbolAddress((void**)&gnbr, g_nbr);

    // ---- encoders -> g_x
    encode_kernel<32><<<(n_ind + 127) / 128, 128>>>(x_ind, W_ind, b_ind, gx, n_ind);
    encode_kernel<48><<<(n_com + 127) / 128, 128>>>(x_com, W_com, b_com,
                                                    gx + (size_t)n_ind * HD, n_com);
    encode_kernel<24><<<(n_tru + 127) / 128, 128>>>(x_tru, W_tru, b_tru,
                                                    gx + (size_t)(n_ind + n_com) * HD, n_tru);

    // ---- CSR build
    int nInt4 = (N + 3) / 4;
    zero_kernel<<<(nInt4 + 255) / 256, 256>>>((float4*)gdeg, nInt4);
    degree_kernel<<<(E + 255) / 256, 256>>>(dst, gdeg, E);
    int nb = (N + 1023) / 1024;
    scan1_kernel<<<nb, 256>>>(gdeg, gexcl, gbsum, N);
    scan2_kernel<<<1, 512>>>(gbsum, nb);
    scan3_kernel<<<(N + 255) / 256, 256>>>(gexcl, gbsum, goff, gcur, N, E);
    bucket_kernel<<<(E + 255) / 256, 256>>>(src, dst, gcur, gnbr, E);

    // ---- SAGE layer 1: g_x -> g_y
    agg_kernel<<<(N * 32 + 255) / 256, 256>>>(gx, goff, gnbr, gagg, N);
    sage_combine_kernel<<<(N + 127) / 128, 128>>>(gx, gagg, W1l, W1r, b1, gy, N);

    // ---- SAGE layer 2: g_y -> g_x
    agg_kernel<<<(N * 32 + 255) / 256, 256>>>(gy, goff, gnbr, gagg, N);
    sage_combine_kernel<<<(N + 127) / 128, 128>>>(gy, gagg, W2l, W2r, b2, gx, N);

    // ---- classifier -> d_out
    classify_kernel<<<(N + 127) / 128, 128>>>(gx, Wc1, bc1, Wc2, bc2, (float*)d_out, N);
}